// round 3
// baseline (speedup 1.0000x reference)
#include <cuda_runtime.h>
#include <cstdint>

#define NV      40962
#define NVP     10242
#define BB      8
#define CIN     64
#define COUT    64
#define KN      7
#define NGROUPS 32
#define MO      256          // 4 feature-matrices * 64 output channels
#define EPS     1e-5f

// ---------------- scratch (static device arrays; no allocation) ----------------
__device__ float Z_buf[(size_t)BB * NVP * MO];   // [b][u][m*64+o], ~84 MB
__device__ float W_t[CIN * MO];                  // [i][mo] repacked coeffs
__device__ float g_sum[BB * NGROUPS];
__device__ float g_sumsq[BB * NGROUPS];

// ---------------- K0: repack coeffs (o,i,m) -> W_t[i][m*64+o] ----------------
__global__ void k_repack(const float* __restrict__ coeffs) {
    int t = blockIdx.x * blockDim.x + threadIdx.x;
    if (t < CIN * MO) {
        int i  = t >> 8;       // 0..63
        int mo = t & 255;
        int m  = mo >> 6;
        int o  = mo & 63;
        W_t[t] = coeffs[(o * CIN + i) * 4 + m];
    }
}

// ---------------- zero group accumulators ----------------
__global__ void k_zero() {
    int t = threadIdx.x;
    if (t < BB * NGROUPS) { g_sum[t] = 0.f; g_sumsq[t] = 0.f; }
}

// ---------------- K1: Z[b][u][mo] = sum_i W_t[i][mo] * x[b][i][u] ----------------
// block: 256 threads, tile = 256 mo x 64 u, 8x8 register tile per thread.
__global__ __launch_bounds__(256, 2) void k_gemm(const float* __restrict__ x) {
    extern __shared__ float smem[];
    float* ws = smem;                 // [64][256]  (i-major)
    float* xs = smem + CIN * MO;      // [64][64]   (i-major)

    const int b  = blockIdx.y;
    const int u0 = blockIdx.x * 64;
    const int t  = threadIdx.x;

    // load W tile (identical for every block; L2-resident)
    for (int idx = t; idx < CIN * MO; idx += 256)
        ws[idx] = W_t[idx];
    // load x tile
    for (int idx = t; idx < CIN * 64; idx += 256) {
        int i = idx >> 6, u = idx & 63;
        int uu = u0 + u;
        xs[i * 64 + u] = (uu < NVP) ? x[((size_t)b * CIN + i) * NVP + uu] : 0.f;
    }
    __syncthreads();

    const int tx  = t & 7;        // u sub-tile
    const int ty  = t >> 3;       // mo sub-tile (0..31)
    const int mo0 = ty * 8;
    const int ut  = tx * 8;

    float acc[8][8];
#pragma unroll
    for (int r = 0; r < 8; r++)
#pragma unroll
        for (int c = 0; c < 8; c++) acc[r][c] = 0.f;

#pragma unroll 4
    for (int i = 0; i < CIN; i++) {
        float4 wa = *(const float4*)&ws[i * MO + mo0];
        float4 wb = *(const float4*)&ws[i * MO + mo0 + 4];
        float4 xa = *(const float4*)&xs[i * 64 + ut];
        float4 xb = *(const float4*)&xs[i * 64 + ut + 4];
        float w[8]  = {wa.x, wa.y, wa.z, wa.w, wb.x, wb.y, wb.z, wb.w};
        float xv[8] = {xa.x, xa.y, xa.z, xa.w, xb.x, xb.y, xb.z, xb.w};
#pragma unroll
        for (int r = 0; r < 8; r++)
#pragma unroll
            for (int c = 0; c < 8; c++)
                acc[r][c] += w[r] * xv[c];
    }

    // store Z[b][u][mo] (mo contiguous)
#pragma unroll
    for (int c = 0; c < 8; c++) {
        int uu = u0 + ut + c;
        if (uu < NVP) {
            float* zp = &Z_buf[((size_t)b * NVP + uu) * MO + mo0];
            *(float4*)zp       = make_float4(acc[0][c], acc[1][c], acc[2][c], acc[3][c]);
            *(float4*)(zp + 4) = make_float4(acc[4][c], acc[5][c], acc[6][c], acc[7][c]);
        }
    }
}

// ---------------- K2: gather + bias, write pre-norm out, accumulate GN stats ---
// block: 256 threads = 64 channels x 4 v-lanes, v-tile of 32 per block.
// Each warp owns a single v per iteration -> uniform idx/weight loads, uniform branch.
__global__ __launch_bounds__(256) void k_gather(
    const float* __restrict__ Lv, const float* __restrict__ EWv,
    const float* __restrict__ NSv, const int* __restrict__ nbr,
    const float* __restrict__ bias, float* __restrict__ out)
{
    __shared__ float smt[64][33];     // padded transpose tile
    __shared__ float s_s[NGROUPS], s_q[NGROUPS];

    const int b  = blockIdx.y;
    const int v0 = blockIdx.x * 32;
    const int t  = threadIdx.x;
    const int o  = t & 63;
    const int vl = t >> 6;            // 0..3

    if (t < NGROUPS) { s_s[t] = 0.f; s_q[t] = 0.f; }
    __syncthreads();

    const float bo = bias[o];
    const float* zb = &Z_buf[(size_t)b * NVP * MO];
    float lsum = 0.f, lsq = 0.f;

#pragma unroll 1
    for (int it = 0; it < 8; it++) {
        const int v = v0 + it * 4 + vl;
        float acc = 0.f;
        if (v < NV) {
            acc = bo;
            if (v < NVP) acc += zb[(size_t)v * MO + o];
#pragma unroll
            for (int k = 0; k < KN; k++) {
                int nk = __ldg(&nbr[v * KN + k]);
                if (nk < NVP) {
                    const float* zp = &zb[(size_t)nk * MO];
                    float lw = __ldg(&Lv[v * KN + k]);
                    float ew = __ldg(&EWv[v * KN + k]);
                    float nw = __ldg(&NSv[v * KN + k]);
                    acc += lw * zp[64 + o] + ew * zp[128 + o] + nw * zp[192 + o];
                }
            }
            lsum += acc;
            lsq  += acc * acc;
        }
        smt[o][it * 4 + vl] = acc;
    }

    // pairwise (2g, 2g+1) channel reduce within warp, then shared atomics
    lsum += __shfl_down_sync(0xffffffffu, lsum, 1);
    lsq  += __shfl_down_sync(0xffffffffu, lsq, 1);
    if ((o & 1) == 0) {
        atomicAdd(&s_s[o >> 1], lsum);
        atomicAdd(&s_q[o >> 1], lsq);
    }
    __syncthreads();
    if (t < NGROUPS) {
        atomicAdd(&g_sum[b * NGROUPS + t],   s_s[t]);
        atomicAdd(&g_sumsq[b * NGROUPS + t], s_q[t]);
    }

    // coalesced store of the (b, o, v0..v0+31) tile
    for (int j = t; j < 64 * 32; j += 256) {
        int oo = j >> 5, c = j & 31;
        int v = v0 + c;
        if (v < NV)
            out[((size_t)b * COUT + oo) * NV + v] = smt[oo][c];
    }
}

// ---------------- K3: in-place GroupNorm affine + ReLU ----------------
__global__ void k_norm(float* __restrict__ out,
                       const float* __restrict__ gamma,
                       const float* __restrict__ beta)
{
    const unsigned HALF = NV / 2;                       // 20481 (NV even)
    const size_t total = (size_t)BB * COUT * HALF;
    size_t p = (size_t)blockIdx.x * blockDim.x + threadIdx.x;
    if (p >= total) return;

    unsigned bo = (unsigned)(p / HALF);
    int b = bo >> 6;
    int o = bo & 63;
    int g = b * NGROUPS + (o >> 1);

    const float invN = 1.f / (2.f * (float)NV);
    float mean = g_sum[g] * invN;
    float var  = g_sumsq[g] * invN - mean * mean;
    float inv  = rsqrtf(var + EPS);
    float a = inv * gamma[o];
    float c = beta[o] - mean * a;

    float2 vv = ((float2*)out)[p];
    vv.x = fmaxf(vv.x * a + c, 0.f);
    vv.y = fmaxf(vv.y * a + c, 0.f);
    ((float2*)out)[p] = vv;
}

// ---------------- launch ----------------
extern "C" void kernel_launch(void* const* d_in, const int* in_sizes, int n_in,
                              void* d_out, int out_size) {
    const float* x      = (const float*)d_in[0];
    const float* Lv     = (const float*)d_in[1];
    const float* EWv    = (const float*)d_in[2];
    const float* NSv    = (const float*)d_in[3];
    const float* coeffs = (const float*)d_in[4];
    const float* bias   = (const float*)d_in[5];
    const float* gamma  = (const float*)d_in[6];
    const float* beta   = (const float*)d_in[7];
    const int*   nbr    = (const int*)d_in[8];
    float* out = (float*)d_out;

    const int smem_gemm = (CIN * MO + CIN * 64) * (int)sizeof(float);  // 81920 B
    cudaFuncSetAttribute(k_gemm, cudaFuncAttributeMaxDynamicSharedMemorySize, smem_gemm);

    k_repack<<<(CIN * MO + 255) / 256, 256>>>(coeffs);
    k_zero<<<1, 256>>>();

    dim3 g1((NVP + 63) / 64, BB);
    k_gemm<<<g1, 256, smem_gemm>>>(x);

    dim3 g2((NV + 31) / 32, BB);
    k_gather<<<g2, 256>>>(Lv, EWv, NSv, nbr, bias, out);

    const unsigned HALF = NV / 2;
    size_t total = (size_t)BB * COUT * HALF;
    k_norm<<<(unsigned)((total + 255) / 256), 256>>>(out, gamma, beta);
}

// round 6
// speedup vs baseline: 1.1806x; 1.1806x over previous
#include <cuda_runtime.h>
#include <cstdint>

#define NV      40962
#define NVP     10242
#define BB      8
#define CIN     64
#define COUT    64
#define KN      7
#define NGROUPS 32
#define MO      256          // 4 feature-matrices * 64 output channels
#define EPS     1e-5f

// ---------------- scratch (static device arrays; no allocation) ----------------
__device__ float  Z_buf[(size_t)BB * NVP * MO];   // [b][u][m*64+o], ~84 MB
__device__ float  W_t[CIN * MO];                  // [i][mo] repacked coeffs
__device__ float  g_sum[BB * NGROUPS];
__device__ float  g_sumsq[BB * NGROUPS];
__device__ float  g_a[BB * COUT];
__device__ float  g_c[BB * COUT];
__device__ float4 g_pack[(size_t)NV * KN];        // {rowoff_as_float, lw, ew, nw}
__device__ int    g_cnt[NV];

// ---------------- K0: repack coeffs (o,i,m) -> W_t[i][m*64+o] ----------------
__global__ void k_repack(const float* __restrict__ coeffs) {
    int t = blockIdx.x * blockDim.x + threadIdx.x;
    if (t < CIN * MO) {
        int i  = t >> 8;       // 0..63
        int mo = t & 255;
        int m  = mo >> 6;
        int o  = mo & 63;
        W_t[t] = coeffs[(o * CIN + i) * 4 + m];
    }
}

// ---------------- zero group accumulators ----------------
__global__ void k_zero() {
    int t = threadIdx.x;
    if (t < BB * NGROUPS) { g_sum[t] = 0.f; g_sumsq[t] = 0.f; }
}

// ---------------- K0b: compact valid neighbors (nk < NVP) per vertex ----------
// Stores pre-scaled row offset nk*MO so gather does zero index math.
__global__ void k_compact(const int* __restrict__ nbr,
                          const float* __restrict__ Lv,
                          const float* __restrict__ EWv,
                          const float* __restrict__ NSv) {
    int v = blockIdx.x * blockDim.x + threadIdx.x;
    if (v >= NV) return;
    int c = 0;
#pragma unroll
    for (int k = 0; k < KN; k++) {
        int nk = nbr[v * KN + k];
        if (nk < NVP) {
            g_pack[(size_t)v * KN + c] =
                make_float4(__int_as_float(nk << 8),   // nk*MO
                            Lv[v * KN + k], EWv[v * KN + k], NSv[v * KN + k]);
            c++;
        }
    }
    g_cnt[v] = c;
}

// ---------------- K1: Z[b][u][mo] = sum_i W_t[i][mo] * x[b][i][u] ----------------
__global__ __launch_bounds__(256, 2) void k_gemm(const float* __restrict__ x) {
    extern __shared__ float smem[];
    float* ws = smem;                 // [64][256]  (i-major)
    float* xs = smem + CIN * MO;      // [64][64]   (i-major)

    const int b  = blockIdx.y;
    const int u0 = blockIdx.x * 64;
    const int t  = threadIdx.x;

    for (int idx = t; idx < CIN * MO; idx += 256)
        ws[idx] = W_t[idx];
    for (int idx = t; idx < CIN * 64; idx += 256) {
        int i = idx >> 6, u = idx & 63;
        int uu = u0 + u;
        xs[i * 64 + u] = (uu < NVP) ? x[((size_t)b * CIN + i) * NVP + uu] : 0.f;
    }
    __syncthreads();

    const int tx  = t & 7;
    const int ty  = t >> 3;
    const int mo0 = ty * 8;
    const int ut  = tx * 8;

    float acc[8][8];
#pragma unroll
    for (int r = 0; r < 8; r++)
#pragma unroll
        for (int c = 0; c < 8; c++) acc[r][c] = 0.f;

#pragma unroll 4
    for (int i = 0; i < CIN; i++) {
        float4 wa = *(const float4*)&ws[i * MO + mo0];
        float4 wb = *(const float4*)&ws[i * MO + mo0 + 4];
        float4 xa = *(const float4*)&xs[i * 64 + ut];
        float4 xb = *(const float4*)&xs[i * 64 + ut + 4];
        float w[8]  = {wa.x, wa.y, wa.z, wa.w, wb.x, wb.y, wb.z, wb.w};
        float xv[8] = {xa.x, xa.y, xa.z, xa.w, xb.x, xb.y, xb.z, xb.w};
#pragma unroll
        for (int r = 0; r < 8; r++)
#pragma unroll
            for (int c = 0; c < 8; c++)
                acc[r][c] += w[r] * xv[c];
    }

#pragma unroll
    for (int c = 0; c < 8; c++) {
        int uu = u0 + ut + c;
        if (uu < NVP) {
            float* zp = &Z_buf[((size_t)b * NVP + uu) * MO + mo0];
            *(float4*)zp       = make_float4(acc[0][c], acc[1][c], acc[2][c], acc[3][c]);
            *(float4*)(zp + 4) = make_float4(acc[4][c], acc[5][c], acc[6][c], acc[7][c]);
        }
    }
}

// ---------------- K2: gather + bias from compacted lists, GN stats ----------
// block: 256 threads = 64 channels x 4 v-lanes; 32 vertices per block.
// Packed neighbor table staged in smem (coalesced); inner loop only over
// VALID neighbors (~1.75 avg of 7). Two independent accumulation chains per
// warp for memory-level parallelism.
__global__ __launch_bounds__(256) void k_gather(const float* __restrict__ bias,
                                                float* __restrict__ out)
{
    __shared__ float4 s_pack[32 * KN];
    __shared__ int    s_cnt[32];
    __shared__ float  smt[64][33];     // padded transpose tile
    __shared__ float  s_s[NGROUPS], s_q[NGROUPS];

    const int b  = blockIdx.y;
    const int v0 = blockIdx.x * 32;
    const int t  = threadIdx.x;
    const int o  = t & 63;
    const int vl = t >> 6;            // 0..3
    const int nvleft = min(32, NV - v0);

    if (t < NGROUPS) { s_s[t] = 0.f; s_q[t] = 0.f; }
    if (t < 32) s_cnt[t] = (t < nvleft) ? g_cnt[v0 + t] : 0;
    for (int j = t; j < nvleft * KN; j += 256)
        s_pack[j] = g_pack[(size_t)v0 * KN + j];
    __syncthreads();

    const float bo = bias[o];
    const float* zb = &Z_buf[(size_t)b * NVP * MO];
    float lsum = 0.f, lsq = 0.f;

#pragma unroll
    for (int it = 0; it < 4; it++) {
        const int c0 = it * 8 + vl * 2;     // columns c0, c0+1 of this tile
        const int va = v0 + c0;
        const int vb = va + 1;
        const bool okA = va < NV;
        const bool okB = vb < NV;

        float aA = 0.f, aB = 0.f;
        if (okA) { aA = bo; if (va < NVP) aA += zb[(size_t)va * MO + o]; }
        if (okB) { aB = bo; if (vb < NVP) aB += zb[(size_t)vb * MO + o]; }

        const int ca = okA ? s_cnt[c0]     : 0;
        const int cb = okB ? s_cnt[c0 + 1] : 0;
        const float4* pa = &s_pack[c0 * KN];
        const float4* pb = &s_pack[(c0 + 1) * KN];
        const int cm = max(ca, cb);

        for (int j = 0; j < cm; j++) {
            if (j < ca) {
                float4 e = pa[j];
                const float* zp = zb + __float_as_int(e.x);
                aA += e.y * zp[64 + o] + e.z * zp[128 + o] + e.w * zp[192 + o];
            }
            if (j < cb) {
                float4 e = pb[j];
                const float* zp = zb + __float_as_int(e.x);
                aB += e.y * zp[64 + o] + e.z * zp[128 + o] + e.w * zp[192 + o];
            }
        }

        if (okA) { lsum += aA; lsq += aA * aA; }
        if (okB) { lsum += aB; lsq += aB * aB; }
        smt[o][c0]     = aA;
        smt[o][c0 + 1] = aB;
    }

    // pairwise (2g, 2g+1) channel reduce within warp, then shared atomics
    lsum += __shfl_down_sync(0xffffffffu, lsum, 1);
    lsq  += __shfl_down_sync(0xffffffffu, lsq, 1);
    if ((o & 1) == 0) {
        atomicAdd(&s_s[o >> 1], lsum);
        atomicAdd(&s_q[o >> 1], lsq);
    }
    __syncthreads();
    if (t < NGROUPS) {
        atomicAdd(&g_sum[b * NGROUPS + t],   s_s[t]);
        atomicAdd(&g_sumsq[b * NGROUPS + t], s_q[t]);
    }

    // coalesced store of the (b, o, v0..v0+31) tile
    for (int j = t; j < 64 * 32; j += 256) {
        int oo = j >> 5, c = j & 31;
        int v = v0 + c;
        if (v < NV)
            out[((size_t)b * COUT + oo) * NV + v] = smt[oo][c];
    }
}

// ---------------- K2b: finalize per-(b,o) affine coefficients ----------------
__global__ void k_final(const float* __restrict__ gamma,
                        const float* __restrict__ beta) {
    int t = threadIdx.x;
    if (t < BB * COUT) {
        int o = t & 63;
        int g = ((t >> 6) * NGROUPS) + (o >> 1);
        const float invN = 1.f / (2.f * (float)NV);
        float mean = g_sum[g] * invN;
        float var  = g_sumsq[g] * invN - mean * mean;
        float inv  = rsqrtf(var + EPS);
        float a = inv * gamma[o];
        g_a[t] = a;
        g_c[t] = beta[o] - mean * a;
    }
}

// ---------------- K3: in-place GroupNorm affine + ReLU ----------------
__global__ void k_norm(float* __restrict__ out) {
    const unsigned HALF = NV / 2;                       // 20481
    const size_t total = (size_t)BB * COUT * HALF;
    size_t p = (size_t)blockIdx.x * blockDim.x + threadIdx.x;
    if (p >= total) return;

    unsigned bo = (unsigned)(p / HALF);
    float a = g_a[bo];
    float c = g_c[bo];

    float2 vv = ((float2*)out)[p];
    vv.x = fmaxf(vv.x * a + c, 0.f);
    vv.y = fmaxf(vv.y * a + c, 0.f);
    ((float2*)out)[p] = vv;
}

// ---------------- launch ----------------
extern "C" void kernel_launch(void* const* d_in, const int* in_sizes, int n_in,
                              void* d_out, int out_size) {
    const float* x      = (const float*)d_in[0];
    const float* Lv     = (const float*)d_in[1];
    const float* EWv    = (const float*)d_in[2];
    const float* NSv    = (const float*)d_in[3];
    const float* coeffs = (const float*)d_in[4];
    const float* bias   = (const float*)d_in[5];
    const float* gamma  = (const float*)d_in[6];
    const float* beta   = (const float*)d_in[7];
    const int*   nbr    = (const int*)d_in[8];
    float* out = (float*)d_out;

    const int smem_gemm = (CIN * MO + CIN * 64) * (int)sizeof(float);  // 81920 B
    cudaFuncSetAttribute(k_gemm, cudaFuncAttributeMaxDynamicSharedMemorySize, smem_gemm);

    k_repack<<<(CIN * MO + 255) / 256, 256>>>(coeffs);
    k_zero<<<1, 256>>>();
    k_compact<<<(NV + 255) / 256, 256>>>(nbr, Lv, EWv, NSv);

    dim3 g1((NVP + 63) / 64, BB);
    k_gemm<<<g1, 256, smem_gemm>>>(x);

    dim3 g2((NV + 31) / 32, BB);
    k_gather<<<g2, 256>>>(bias, out);

    k_final<<<1, 512>>>(gamma, beta);

    const unsigned HALF = NV / 2;
    size_t total = (size_t)BB * COUT * HALF;
    k_norm<<<(unsigned)((total + 255) / 256), 256>>>(out);
}

// round 8
// speedup vs baseline: 1.4986x; 1.2694x over previous
#include <cuda_runtime.h>
#include <cstdint>

#define NV      40962
#define NVP     10242
#define BB      8
#define CIN     64
#define COUT    64
#define KN      7
#define NGROUPS 32
#define MO      256          // 4 feature-matrices * 64 output channels
#define EPS     1e-5f
#define KC      32           // K-chunk for gemm smem staging

// ---------------- scratch (static device arrays; no allocation) ----------------
__device__ __align__(128) float  Z_buf[(size_t)BB * NVP * MO];   // [b][u][m*64+o]
__device__ __align__(16)  float  W_t[CIN * MO];                  // [i][mo]
__device__ float  g_sum[BB * NGROUPS];
__device__ float  g_sumsq[BB * NGROUPS];
__device__ float  g_a[BB * COUT];
__device__ float  g_c[BB * COUT];
__device__ __align__(16) float4 g_pack[(size_t)NV * KN];         // {rowoff, lw, ew, nw}
__device__ int    g_cnt[NV];

// ---------------- f32x2 helpers (Blackwell packed fp32 pipe) ----------------
__device__ __forceinline__ unsigned long long splat2(float v) {
    unsigned long long r;
    asm("mov.b64 %0, {%1, %1};" : "=l"(r) : "f"(v));
    return r;
}
__device__ __forceinline__ unsigned long long fma2(unsigned long long a,
                                                   unsigned long long b,
                                                   unsigned long long c) {
    unsigned long long d;
    asm("fma.rn.f32x2 %0, %1, %2, %3;" : "=l"(d) : "l"(a), "l"(b), "l"(c));
    return d;
}
__device__ __forceinline__ float2 unpack2(unsigned long long v) {
    float lo, hi;
    asm("mov.b64 {%0, %1}, %2;" : "=f"(lo), "=f"(hi) : "l"(v));
    return make_float2(lo, hi);
}

// ---------------- K0: repack coeffs (o,i,m) -> W_t[i][m*64+o] ----------------
__global__ void k_repack(const float* __restrict__ coeffs) {
    int t = blockIdx.x * blockDim.x + threadIdx.x;
    if (t < CIN * MO) {
        int i  = t >> 8;
        int mo = t & 255;
        int m  = mo >> 6;
        int o  = mo & 63;
        W_t[t] = coeffs[(o * CIN + i) * 4 + m];
    }
}

// ---------------- zero group accumulators ----------------
__global__ void k_zero() {
    int t = threadIdx.x;
    if (t < BB * NGROUPS) { g_sum[t] = 0.f; g_sumsq[t] = 0.f; }
}

// ---------------- K0b: compact valid neighbors (nk < NVP) per vertex ----------
__global__ void k_compact(const int* __restrict__ nbr,
                          const float* __restrict__ Lv,
                          const float* __restrict__ EWv,
                          const float* __restrict__ NSv) {
    int v = blockIdx.x * blockDim.x + threadIdx.x;
    if (v >= NV) return;
    int c = 0;
#pragma unroll
    for (int k = 0; k < KN; k++) {
        int nk = nbr[v * KN + k];
        if (nk < NVP) {
            g_pack[(size_t)v * KN + c] =
                make_float4(__int_as_float(nk << 8),   // nk*MO
                            Lv[v * KN + k], EWv[v * KN + k], NSv[v * KN + k]);
            c++;
        }
    }
    g_cnt[v] = c;
}

// ---------------- K1: Z[b][u][mo] = sum_i W_t[i][mo] * x[b][i][u] ----------------
// block 256 thr: tile 256mo x 32u. thread: 8mo x 4u via 16 f32x2 accumulators
// vectorized along mo (W pairs natural float2, x splatted). K chunked at 32
// so smem = 36KB -> 3+ CTAs/SM.
__global__ __launch_bounds__(256, 3) void k_gemm(const float* __restrict__ x) {
    __shared__ __align__(16) float ws[KC * MO];   // 32KB
    __shared__ __align__(16) float xs[KC * 32];   // 4KB

    const int b   = blockIdx.y;
    const int u0  = blockIdx.x * 32;
    const int t   = threadIdx.x;
    const int tx  = t & 7;          // u group: 4 u each
    const int ty  = t >> 3;         // mo group: 8 mo each
    const int mo0 = ty * 8;
    const int ub  = tx * 4;

    unsigned long long acc[4][4];   // [u][mo-pair]
#pragma unroll
    for (int u = 0; u < 4; u++)
#pragma unroll
        for (int p = 0; p < 4; p++) acc[u][p] = 0ull;

#pragma unroll 1
    for (int kc = 0; kc < CIN / KC; kc++) {
        // stage W chunk (coalesced float4)
        const float4* wsrc = (const float4*)(W_t + kc * KC * MO);
#pragma unroll
        for (int j = 0; j < (KC * MO / 4) / 256; j++)      // 8 iters
            ((float4*)ws)[t + j * 256] = wsrc[t + j * 256];
        // stage x chunk as float2 (rows only 8B aligned)
#pragma unroll
        for (int j = 0; j < 2; j++) {
            int f2 = t + j * 256;
            int i  = f2 >> 4;           // 16 float2 per 32-wide row
            int u  = (f2 & 15) * 2;
            int uu = u0 + u;
            float2 val = make_float2(0.f, 0.f);
            if (uu < NVP)
                val = *(const float2*)&x[((size_t)(b * CIN) + kc * KC + i) * NVP + uu];
            *(float2*)&xs[i * 32 + u] = val;
        }
        __syncthreads();

#pragma unroll 4
        for (int i = 0; i < KC; i++) {
            const ulonglong2 wA = *(const ulonglong2*)&ws[i * MO + mo0];
            const ulonglong2 wB = *(const ulonglong2*)&ws[i * MO + mo0 + 4];
            const float4 xv = *(const float4*)&xs[i * 32 + ub];
            unsigned long long wp[4] = {wA.x, wA.y, wB.x, wB.y};
            unsigned long long xp[4] = {splat2(xv.x), splat2(xv.y),
                                        splat2(xv.z), splat2(xv.w)};
#pragma unroll
            for (int u = 0; u < 4; u++)
#pragma unroll
                for (int p = 0; p < 4; p++)
                    acc[u][p] = fma2(wp[p], xp[u], acc[u][p]);
        }
        __syncthreads();
    }

    // store Z[b][uu][mo0..mo0+7]
#pragma unroll
    for (int u = 0; u < 4; u++) {
        int uu = u0 + ub + u;
        if (uu < NVP) {
            float2 p0 = unpack2(acc[u][0]);
            float2 p1 = unpack2(acc[u][1]);
            float2 p2 = unpack2(acc[u][2]);
            float2 p3 = unpack2(acc[u][3]);
            float* zp = &Z_buf[((size_t)b * NVP + uu) * MO + mo0];
            *(float4*)zp       = make_float4(p0.x, p0.y, p1.x, p1.y);
            *(float4*)(zp + 4) = make_float4(p2.x, p2.y, p3.x, p3.y);
        }
    }
}

// ---------------- K2: gather + bias from compacted lists, GN stats ----------
__global__ __launch_bounds__(256) void k_gather(const float* __restrict__ bias,
                                                float* __restrict__ out)
{
    __shared__ float4 s_pack[32 * KN];
    __shared__ int    s_cnt[32];
    __shared__ float  smt[64][33];
    __shared__ float  s_s[NGROUPS], s_q[NGROUPS];

    const int b  = blockIdx.y;
    const int v0 = blockIdx.x * 32;
    const int t  = threadIdx.x;
    const int o  = t & 63;
    const int vl = t >> 6;            // 0..3
    const int nvleft = min(32, NV - v0);

    if (t < NGROUPS) { s_s[t] = 0.f; s_q[t] = 0.f; }
    if (t < 32) s_cnt[t] = (t < nvleft) ? g_cnt[v0 + t] : 0;
    for (int j = t; j < nvleft * KN; j += 256)
        s_pack[j] = g_pack[(size_t)v0 * KN + j];
    __syncthreads();

    const float bo = bias[o];
    const float* zb = &Z_buf[(size_t)b * NVP * MO];
    float lsum = 0.f, lsq = 0.f;

#pragma unroll
    for (int it = 0; it < 4; it++) {
        const int c0 = it * 8 + vl * 2;
        const int va = v0 + c0;
        const int vb = va + 1;
        const bool okA = va < NV;
        const bool okB = vb < NV;

        float aA = 0.f, aB = 0.f;
        if (okA) { aA = bo; if (va < NVP) aA += zb[(size_t)va * MO + o]; }
        if (okB) { aB = bo; if (vb < NVP) aB += zb[(size_t)vb * MO + o]; }

        const int ca = okA ? s_cnt[c0]     : 0;
        const int cb = okB ? s_cnt[c0 + 1] : 0;
        const float4* pa = &s_pack[c0 * KN];
        const float4* pb = &s_pack[(c0 + 1) * KN];
        const int cm = max(ca, cb);

        for (int j = 0; j < cm; j++) {
            if (j < ca) {
                float4 e = pa[j];
                const float* zp = zb + __float_as_int(e.x);
                aA += e.y * zp[64 + o] + e.z * zp[128 + o] + e.w * zp[192 + o];
            }
            if (j < cb) {
                float4 e = pb[j];
                const float* zp = zb + __float_as_int(e.x);
                aB += e.y * zp[64 + o] + e.z * zp[128 + o] + e.w * zp[192 + o];
            }
        }

        if (okA) { lsum += aA; lsq += aA * aA; }
        if (okB) { lsum += aB; lsq += aB * aB; }
        smt[o][c0]     = aA;
        smt[o][c0 + 1] = aB;
    }

    lsum += __shfl_down_sync(0xffffffffu, lsum, 1);
    lsq  += __shfl_down_sync(0xffffffffu, lsq, 1);
    if ((o & 1) == 0) {
        atomicAdd(&s_s[o >> 1], lsum);
        atomicAdd(&s_q[o >> 1], lsq);
    }
    __syncthreads();
    if (t < NGROUPS) {
        atomicAdd(&g_sum[b * NGROUPS + t],   s_s[t]);
        atomicAdd(&g_sumsq[b * NGROUPS + t], s_q[t]);
    }

    for (int j = t; j < 64 * 32; j += 256) {
        int oo = j >> 5, c = j & 31;
        int v = v0 + c;
        if (v < NV)
            out[((size_t)b * COUT + oo) * NV + v] = smt[oo][c];
    }
}

// ---------------- K2b: finalize per-(b,o) affine coefficients ----------------
__global__ void k_final(const float* __restrict__ gamma,
                        const float* __restrict__ beta) {
    int t = threadIdx.x;
    if (t < BB * COUT) {
        int o = t & 63;
        int g = ((t >> 6) * NGROUPS) + (o >> 1);
        const float invN = 1.f / (2.f * (float)NV);
        float mean = g_sum[g] * invN;
        float var  = g_sumsq[g] * invN - mean * mean;
        float inv  = rsqrtf(var + EPS);
        float a = inv * gamma[o];
        g_a[t] = a;
        g_c[t] = beta[o] - mean * a;
    }
}

// ---------------- K3: in-place GroupNorm affine + ReLU ----------------
__global__ void k_norm(float* __restrict__ out) {
    const unsigned HALF = NV / 2;                       // 20481
    const size_t total = (size_t)BB * COUT * HALF;
    size_t p = (size_t)blockIdx.x * blockDim.x + threadIdx.x;
    if (p >= total) return;

    unsigned bo = (unsigned)(p / HALF);
    float a = g_a[bo];
    float c = g_c[bo];

    float2 vv = ((float2*)out)[p];
    vv.x = fmaxf(vv.x * a + c, 0.f);
    vv.y = fmaxf(vv.y * a + c, 0.f);
    ((float2*)out)[p] = vv;
}

// ---------------- launch ----------------
extern "C" void kernel_launch(void* const* d_in, const int* in_sizes, int n_in,
                              void* d_out, int out_size) {
    const float* x      = (const float*)d_in[0];
    const float* Lv     = (const float*)d_in[1];
    const float* EWv    = (const float*)d_in[2];
    const float* NSv    = (const float*)d_in[3];
    const float* coeffs = (const float*)d_in[4];
    const float* bias   = (const float*)d_in[5];
    const float* gamma  = (const float*)d_in[6];
    const float* beta   = (const float*)d_in[7];
    const int*   nbr    = (const int*)d_in[8];
    float* out = (float*)d_out;

    k_repack<<<(CIN * MO + 255) / 256, 256>>>(coeffs);
    k_zero<<<1, 256>>>();
    k_compact<<<(NV + 255) / 256, 256>>>(nbr, Lv, EWv, NSv);

    dim3 g1((NVP + 31) / 32, BB);
    k_gemm<<<g1, 256>>>(x);

    dim3 g2((NV + 31) / 32, BB);
    k_gather<<<g2, 256>>>(bias, out);

    k_final<<<1, 512>>>(gamma, beta);

    const unsigned HALF = NV / 2;
    size_t total = (size_t)BB * COUT * HALF;
    k_norm<<<(unsigned)((total + 255) / 256), 256>>>(out);
}

// round 9
// speedup vs baseline: 1.6483x; 1.0999x over previous
#include <cuda_runtime.h>
#include <cstdint>

#define NV      40962
#define NVP     10242
#define BB      8
#define CIN     64
#define COUT    64
#define KN      7
#define NGROUPS 32
#define MO      256          // 4 feature-matrices * 64 output channels
#define EPS     1e-5f
#define KC      32           // K-chunk for gemm smem staging

// ---------------- scratch (static device arrays; no allocation) ----------------
__device__ __align__(128) float  Z_buf[(size_t)BB * NVP * MO];   // [b][u][m*64+o]
__device__ __align__(16)  float  W_t[CIN * MO];                  // [i][mo]
__device__ float  g_sum[BB * NGROUPS];
__device__ float  g_sumsq[BB * NGROUPS];
__device__ float  g_a[BB * COUT];
__device__ float  g_c[BB * COUT];
__device__ __align__(16) float4 g_pack[(size_t)NV * KN];         // {rowoff, lw, ew, nw}
__device__ int    g_cnt[NV];

// ---------------- f32x2 helpers (Blackwell packed fp32 pipe) ----------------
__device__ __forceinline__ unsigned long long splat2(float v) {
    unsigned long long r;
    asm("mov.b64 %0, {%1, %1};" : "=l"(r) : "f"(v));
    return r;
}
__device__ __forceinline__ unsigned long long fma2(unsigned long long a,
                                                   unsigned long long b,
                                                   unsigned long long c) {
    unsigned long long d;
    asm("fma.rn.f32x2 %0, %1, %2, %3;" : "=l"(d) : "l"(a), "l"(b), "l"(c));
    return d;
}
__device__ __forceinline__ float2 unpack2(unsigned long long v) {
    float lo, hi;
    asm("mov.b64 {%0, %1}, %2;" : "=f"(lo), "=f"(hi) : "l"(v));
    return make_float2(lo, hi);
}

// ---------------- K0: prep = repack coeffs + zero stats + compact neighbors ---
__global__ void k_prep(const float* __restrict__ coeffs,
                       const int* __restrict__ nbr,
                       const float* __restrict__ Lv,
                       const float* __restrict__ EWv,
                       const float* __restrict__ NSv) {
    int t = blockIdx.x * blockDim.x + threadIdx.x;

    if (t < CIN * MO) {                   // repack (o,i,m) -> W_t[i][m*64+o]
        int i  = t >> 8;
        int mo = t & 255;
        int m  = mo >> 6;
        int o  = mo & 63;
        W_t[t] = coeffs[(o * CIN + i) * 4 + m];
    }
    if (t < BB * NGROUPS) { g_sum[t] = 0.f; g_sumsq[t] = 0.f; }

    if (t < NV) {                         // compact valid neighbors (nk < NVP)
        int c = 0;
#pragma unroll
        for (int k = 0; k < KN; k++) {
            int nk = nbr[t * KN + k];
            if (nk < NVP) {
                g_pack[(size_t)t * KN + c] =
                    make_float4(__int_as_float(nk << 8),   // nk*MO
                                Lv[t * KN + k], EWv[t * KN + k], NSv[t * KN + k]);
                c++;
            }
        }
        g_cnt[t] = c;
    }
}

// ---------------- K1: Z[b][u][mo] = sum_i W_t[i][mo] * x[b][i][u] ----------------
// block 256 thr: tile 256mo x 64u. thread: 8mo x 8u via 32 f32x2 accumulators
// (vectorized along mo). 64B LDS per 32 FFMA2 = 2B/FFMA2 smem traffic.
__global__ __launch_bounds__(256, 2) void k_gemm(const float* __restrict__ x) {
    __shared__ __align__(16) float ws[KC * MO];   // 32KB
    __shared__ __align__(16) float xs[KC * 64];   // 8KB

    const int b   = blockIdx.y;
    const int u0  = blockIdx.x * 64;
    const int t   = threadIdx.x;
    const int tx  = t & 7;          // u group: 8 u each
    const int ty  = t >> 3;         // mo group: 8 mo each
    const int mo0 = ty * 8;
    const int ub  = tx * 8;

    unsigned long long acc[8][4];   // [u][mo-pair]
#pragma unroll
    for (int u = 0; u < 8; u++)
#pragma unroll
        for (int p = 0; p < 4; p++) acc[u][p] = 0ull;

#pragma unroll 1
    for (int kc = 0; kc < CIN / KC; kc++) {
        // stage W chunk (coalesced float4)
        const float4* wsrc = (const float4*)(W_t + kc * KC * MO);
#pragma unroll
        for (int j = 0; j < (KC * MO / 4) / 256; j++)      // 8 iters
            ((float4*)ws)[t + j * 256] = wsrc[t + j * 256];
        // stage x chunk as float2 (rows only 8B aligned)
#pragma unroll
        for (int j = 0; j < 4; j++) {
            int f2 = t + j * 256;
            int i  = f2 >> 5;           // 32 float2 per 64-wide row
            int u  = (f2 & 31) * 2;
            int uu = u0 + u;
            float2 val = make_float2(0.f, 0.f);
            if (uu < NVP)
                val = *(const float2*)&x[((size_t)(b * CIN) + kc * KC + i) * NVP + uu];
            *(float2*)&xs[i * 64 + u] = val;
        }
        __syncthreads();

#pragma unroll 2
        for (int i = 0; i < KC; i++) {
            const ulonglong2 wA = *(const ulonglong2*)&ws[i * MO + mo0];
            const ulonglong2 wB = *(const ulonglong2*)&ws[i * MO + mo0 + 4];
            const float4 xa = *(const float4*)&xs[i * 64 + ub];
            const float4 xb = *(const float4*)&xs[i * 64 + ub + 4];
            unsigned long long wp[4] = {wA.x, wA.y, wB.x, wB.y};
            unsigned long long xp[8] = {splat2(xa.x), splat2(xa.y),
                                        splat2(xa.z), splat2(xa.w),
                                        splat2(xb.x), splat2(xb.y),
                                        splat2(xb.z), splat2(xb.w)};
#pragma unroll
            for (int u = 0; u < 8; u++)
#pragma unroll
                for (int p = 0; p < 4; p++)
                    acc[u][p] = fma2(wp[p], xp[u], acc[u][p]);
        }
        __syncthreads();
    }

    // store Z[b][uu][mo0..mo0+7]
#pragma unroll
    for (int u = 0; u < 8; u++) {
        int uu = u0 + ub + u;
        if (uu < NVP) {
            float2 p0 = unpack2(acc[u][0]);
            float2 p1 = unpack2(acc[u][1]);
            float2 p2 = unpack2(acc[u][2]);
            float2 p3 = unpack2(acc[u][3]);
            float* zp = &Z_buf[((size_t)b * NVP + uu) * MO + mo0];
            *(float4*)zp       = make_float4(p0.x, p0.y, p1.x, p1.y);
            *(float4*)(zp + 4) = make_float4(p2.x, p2.y, p3.x, p3.y);
        }
    }
}

// ---------------- K2: gather + bias from compacted lists, GN stats ----------
// block 256 thr = 16 channel-quads x 16 v-lanes; 64 vertices per block.
// Each vertex served by 16 lanes doing float4 Z loads (full 256B segment
// per half-warp per LDG.128) -> 4x fewer load issues than scalar form.
__global__ __launch_bounds__(256) void k_gather(const float* __restrict__ bias,
                                                float* __restrict__ out)
{
    __shared__ float4 s_pack[64 * KN];          // 7KB
    __shared__ int    s_cnt[64];
    __shared__ float  smt[64][65];              // [o][v] transpose tile
    __shared__ float  s_s[NGROUPS], s_q[NGROUPS];

    const int b  = blockIdx.y;
    const int v0 = blockIdx.x * 64;
    const int t  = threadIdx.x;
    const int oq = t & 15;          // channel quad
    const int o4 = oq * 4;
    const int vz = t >> 4;          // 0..15
    const int nvleft = min(64, NV - v0);

    if (t < NGROUPS) { s_s[t] = 0.f; s_q[t] = 0.f; }
    if (t < 64) s_cnt[t] = (t < nvleft) ? g_cnt[v0 + t] : 0;
    for (int j = t; j < nvleft * KN; j += 256)
        s_pack[j] = g_pack[(size_t)v0 * KN + j];
    __syncthreads();

    const float4 bo4 = *(const float4*)&bias[o4];
    const float* zb = &Z_buf[(size_t)b * NVP * MO];

    float sE = 0.f, sO = 0.f, qE = 0.f, qO = 0.f;   // groups 2*oq, 2*oq+1

#pragma unroll
    for (int it = 0; it < 4; it++) {
        const int c = it * 16 + vz;
        const int v = v0 + c;
        float4 a = make_float4(0.f, 0.f, 0.f, 0.f);
        if (v < NV) {
            a = bo4;
            if (v < NVP) {
                float4 z0 = *(const float4*)&zb[(size_t)v * MO + o4];
                a.x += z0.x; a.y += z0.y; a.z += z0.z; a.w += z0.w;
            }
            const int cnt = s_cnt[c];
            const float4* pk = &s_pack[c * KN];
            for (int j = 0; j < cnt; j++) {
                float4 e = pk[j];
                const float* zp = zb + __float_as_int(e.x) + o4;
                float4 z1 = *(const float4*)(zp + 64);
                float4 z2 = *(const float4*)(zp + 128);
                float4 z3 = *(const float4*)(zp + 192);
                a.x += e.y * z1.x + e.z * z2.x + e.w * z3.x;
                a.y += e.y * z1.y + e.z * z2.y + e.w * z3.y;
                a.z += e.y * z1.z + e.z * z2.z + e.w * z3.z;
                a.w += e.y * z1.w + e.z * z2.w + e.w * z3.w;
            }
            sE += a.x + a.y; qE += a.x * a.x + a.y * a.y;
            sO += a.z + a.w; qO += a.z * a.z + a.w * a.w;
        }
        smt[o4 + 0][c] = a.x;
        smt[o4 + 1][c] = a.y;
        smt[o4 + 2][c] = a.z;
        smt[o4 + 3][c] = a.w;
    }

    // lanes l and l+16 share oq -> fold, then one atomic set per oq
    sE += __shfl_down_sync(0xffffffffu, sE, 16);
    sO += __shfl_down_sync(0xffffffffu, sO, 16);
    qE += __shfl_down_sync(0xffffffffu, qE, 16);
    qO += __shfl_down_sync(0xffffffffu, qO, 16);
    if ((t & 31) < 16) {
        atomicAdd(&s_s[2 * oq],     sE);
        atomicAdd(&s_s[2 * oq + 1], sO);
        atomicAdd(&s_q[2 * oq],     qE);
        atomicAdd(&s_q[2 * oq + 1], qO);
    }
    __syncthreads();
    if (t < NGROUPS) {
        atomicAdd(&g_sum[b * NGROUPS + t],   s_s[t]);
        atomicAdd(&g_sumsq[b * NGROUPS + t], s_q[t]);
    }

    // coalesced float2 store of the (b, o, v0..v0+63) tile
#pragma unroll
    for (int k = 0; k < 8; k++) {
        int idx = t + k * 256;
        int oo = idx >> 5;          // 64 rows
        int c2 = idx & 31;          // 32 float2 per row
        int v  = v0 + c2 * 2;
        if (v < NV) {               // NV even: pairs never split
            float2 val = make_float2(smt[oo][c2 * 2], smt[oo][c2 * 2 + 1]);
            *(float2*)&out[((size_t)b * COUT + oo) * NV + v] = val;
        }
    }
}

// ---------------- K2b: finalize per-(b,o) affine coefficients ----------------
__global__ void k_final(const float* __restrict__ gamma,
                        const float* __restrict__ beta) {
    int t = threadIdx.x;
    if (t < BB * COUT) {
        int o = t & 63;
        int g = ((t >> 6) * NGROUPS) + (o >> 1);
        const float invN = 1.f / (2.f * (float)NV);
        float mean = g_sum[g] * invN;
        float var  = g_sumsq[g] * invN - mean * mean;
        float inv  = rsqrtf(var + EPS);
        float a = inv * gamma[o];
        g_a[t] = a;
        g_c[t] = beta[o] - mean * a;
    }
}

// ---------------- K3: in-place GroupNorm affine + ReLU ----------------
__global__ void k_norm(float* __restrict__ out) {
    const unsigned HALF = NV / 2;                       // 20481
    const size_t total = (size_t)BB * COUT * HALF;
    size_t p = (size_t)blockIdx.x * blockDim.x + threadIdx.x;
    if (p >= total) return;

    unsigned bo = (unsigned)(p / HALF);
    float a = g_a[bo];
    float c = g_c[bo];

    float2 vv = ((float2*)out)[p];
    vv.x = fmaxf(vv.x * a + c, 0.f);
    vv.y = fmaxf(vv.y * a + c, 0.f);
    ((float2*)out)[p] = vv;
}

// ---------------- launch ----------------
extern "C" void kernel_launch(void* const* d_in, const int* in_sizes, int n_in,
                              void* d_out, int out_size) {
    const float* x      = (const float*)d_in[0];
    const float* Lv     = (const float*)d_in[1];
    const float* EWv    = (const float*)d_in[2];
    const float* NSv    = (const float*)d_in[3];
    const float* coeffs = (const float*)d_in[4];
    const float* bias   = (const float*)d_in[5];
    const float* gamma  = (const float*)d_in[6];
    const float* beta   = (const float*)d_in[7];
    const int*   nbr    = (const int*)d_in[8];
    float* out = (float*)d_out;

    k_prep<<<(NV + 255) / 256, 256>>>(coeffs, nbr, Lv, EWv, NSv);

    dim3 g1((NVP + 63) / 64, BB);
    k_gemm<<<g1, 256>>>(x);

    dim3 g2((NV + 63) / 64, BB);
    k_gather<<<g2, 256>>>(bias, out);

    k_final<<<1, 512>>>(gamma, beta);

    const unsigned HALF = NV / 2;
    size_t total = (size_t)BB * COUT * HALF;
    k_norm<<<(unsigned)((total + 255) / 256), 256>>>(out);
}

// round 11
// speedup vs baseline: 1.6917x; 1.0264x over previous
#include <cuda_runtime.h>
#include <cuda_fp16.h>
#include <cstdint>

#define NV      40962
#define NVP     10242
#define BB      8
#define CIN     64
#define COUT    64
#define KN      7
#define NGROUPS 32
#define MO      256          // 4 feature-matrices * 64 output channels
#define EPS     1e-5f
#define KC      32           // K-chunk for gemm smem staging
#define HALFNV  (NV / 2)     // 20481 float2 per row

// ---------------- scratch (static device arrays; no allocation) ----------------
__device__ __align__(128) __half  Z_buf[(size_t)BB * NVP * MO];  // fp16 Z, 42MB
__device__ __align__(16)  float   W_t[CIN * MO];                 // [i][mo]
__device__ float  g_sum[BB * NGROUPS];
__device__ float  g_sumsq[BB * NGROUPS];
__device__ __align__(16) float4 g_pack[(size_t)NV * KN];         // {rowoff, lw, ew, nw}
__device__ int    g_cnt[NV];

// ---------------- f32x2 helpers (Blackwell packed fp32 pipe) ----------------
__device__ __forceinline__ unsigned long long splat2(float v) {
    unsigned long long r;
    asm("mov.b64 %0, {%1, %1};" : "=l"(r) : "f"(v));
    return r;
}
__device__ __forceinline__ unsigned long long fma2(unsigned long long a,
                                                   unsigned long long b,
                                                   unsigned long long c) {
    unsigned long long d;
    asm("fma.rn.f32x2 %0, %1, %2, %3;" : "=l"(d) : "l"(a), "l"(b), "l"(c));
    return d;
}
__device__ __forceinline__ float2 unpack2(unsigned long long v) {
    float lo, hi;
    asm("mov.b64 {%0, %1}, %2;" : "=f"(lo), "=f"(hi) : "l"(v));
    return make_float2(lo, hi);
}
__device__ __forceinline__ float2 h2f(unsigned u) {
    __half2 h = *reinterpret_cast<__half2*>(&u);
    return __half22float2(h);
}

// ---------------- K0: prep = repack coeffs + zero stats + compact neighbors ---
__global__ void k_prep(const float* __restrict__ coeffs,
                       const int* __restrict__ nbr,
                       const float* __restrict__ Lv,
                       const float* __restrict__ EWv,
                       const float* __restrict__ NSv) {
    int t = blockIdx.x * blockDim.x + threadIdx.x;

    if (t < CIN * MO) {                   // repack (o,i,m) -> W_t[i][m*64+o]
        int i  = t >> 8;
        int mo = t & 255;
        int m  = mo >> 6;
        int o  = mo & 63;
        W_t[t] = coeffs[(o * CIN + i) * 4 + m];
    }
    if (t < BB * NGROUPS) { g_sum[t] = 0.f; g_sumsq[t] = 0.f; }

    if (t < NV) {                         // compact valid neighbors (nk < NVP)
        int c = 0;
#pragma unroll
        for (int k = 0; k < KN; k++) {
            int nk = nbr[t * KN + k];
            if (nk < NVP) {
                g_pack[(size_t)t * KN + c] =
                    make_float4(__int_as_float(nk << 8),   // nk*MO
                                Lv[t * KN + k], EWv[t * KN + k], NSv[t * KN + k]);
                c++;
            }
        }
        g_cnt[t] = c;
    }
}

// ---------------- K1: Z[b][u][mo] = sum_i W_t[i][mo] * x[b][i][u] ----------------
// block 256 thr: tile 256mo x 64u. thread: 8mo x 8u via 32 f32x2 accumulators.
// Epilogue converts to fp16 (one STG.128 per u).
__global__ __launch_bounds__(256, 2) void k_gemm(const float* __restrict__ x) {
    __shared__ __align__(16) float ws[KC * MO];   // 32KB
    __shared__ __align__(16) float xs[KC * 64];   // 8KB

    const int b   = blockIdx.y;
    const int u0  = blockIdx.x * 64;
    const int t   = threadIdx.x;
    const int tx  = t & 7;          // u group: 8 u each
    const int ty  = t >> 3;         // mo group: 8 mo each
    const int mo0 = ty * 8;
    const int ub  = tx * 8;

    unsigned long long acc[8][4];   // [u][mo-pair]
#pragma unroll
    for (int u = 0; u < 8; u++)
#pragma unroll
        for (int p = 0; p < 4; p++) acc[u][p] = 0ull;

#pragma unroll 1
    for (int kc = 0; kc < CIN / KC; kc++) {
        const float4* wsrc = (const float4*)(W_t + kc * KC * MO);
#pragma unroll
        for (int j = 0; j < (KC * MO / 4) / 256; j++)      // 8 iters
            ((float4*)ws)[t + j * 256] = wsrc[t + j * 256];
#pragma unroll
        for (int j = 0; j < 4; j++) {
            int f2 = t + j * 256;
            int i  = f2 >> 5;           // 32 float2 per 64-wide row
            int u  = (f2 & 31) * 2;
            int uu = u0 + u;
            float2 val = make_float2(0.f, 0.f);
            if (uu < NVP)
                val = *(const float2*)&x[((size_t)(b * CIN) + kc * KC + i) * NVP + uu];
            *(float2*)&xs[i * 64 + u] = val;
        }
        __syncthreads();

#pragma unroll 2
        for (int i = 0; i < KC; i++) {
            const ulonglong2 wA = *(const ulonglong2*)&ws[i * MO + mo0];
            const ulonglong2 wB = *(const ulonglong2*)&ws[i * MO + mo0 + 4];
            const float4 xa = *(const float4*)&xs[i * 64 + ub];
            const float4 xb = *(const float4*)&xs[i * 64 + ub + 4];
            unsigned long long wp[4] = {wA.x, wA.y, wB.x, wB.y};
            unsigned long long xp[8] = {splat2(xa.x), splat2(xa.y),
                                        splat2(xa.z), splat2(xa.w),
                                        splat2(xb.x), splat2(xb.y),
                                        splat2(xb.z), splat2(xb.w)};
#pragma unroll
            for (int u = 0; u < 8; u++)
#pragma unroll
                for (int p = 0; p < 4; p++)
                    acc[u][p] = fma2(wp[p], xp[u], acc[u][p]);
        }
        __syncthreads();
    }

    // store Z[b][uu][mo0..mo0+7] as fp16 (16B per u)
#pragma unroll
    for (int u = 0; u < 8; u++) {
        int uu = u0 + ub + u;
        if (uu < NVP) {
            float2 p0 = unpack2(acc[u][0]);
            float2 p1 = unpack2(acc[u][1]);
            float2 p2 = unpack2(acc[u][2]);
            float2 p3 = unpack2(acc[u][3]);
            __half2 q0 = __floats2half2_rn(p0.x, p0.y);
            __half2 q1 = __floats2half2_rn(p1.x, p1.y);
            __half2 q2 = __floats2half2_rn(p2.x, p2.y);
            __half2 q3 = __floats2half2_rn(p3.x, p3.y);
            uint4 pk;
            pk.x = *reinterpret_cast<unsigned*>(&q0);
            pk.y = *reinterpret_cast<unsigned*>(&q1);
            pk.z = *reinterpret_cast<unsigned*>(&q2);
            pk.w = *reinterpret_cast<unsigned*>(&q3);
            *(uint4*)&Z_buf[((size_t)b * NVP + uu) * MO + mo0] = pk;
        }
    }
}

// ---------------- K2: gather + bias from compacted lists, GN stats ----------
// block 256 thr = 16 channel-quads x 16 v-lanes; 64 vertices per block.
// fp16 Z: each segment per quad is one LDG.64 (half the wavefronts of fp32).
__global__ __launch_bounds__(256) void k_gather(const float* __restrict__ bias,
                                                float* __restrict__ out)
{
    __shared__ float4 s_pack[64 * KN];          // 7KB
    __shared__ int    s_cnt[64];
    __shared__ float  smt[64][65];              // [o][v] transpose tile
    __shared__ float  s_s[NGROUPS], s_q[NGROUPS];

    const int b  = blockIdx.y;
    const int v0 = blockIdx.x * 64;
    const int t  = threadIdx.x;
    const int oq = t & 15;          // channel quad
    const int o4 = oq * 4;
    const int vz = t >> 4;          // 0..15
    const int nvleft = min(64, NV - v0);

    if (t < NGROUPS) { s_s[t] = 0.f; s_q[t] = 0.f; }
    if (t < 64) s_cnt[t] = (t < nvleft) ? g_cnt[v0 + t] : 0;
    for (int j = t; j < nvleft * KN; j += 256)
        s_pack[j] = g_pack[(size_t)v0 * KN + j];
    __syncthreads();

    const float4 bo4 = *(const float4*)&bias[o4];
    const __half* zb = &Z_buf[(size_t)b * NVP * MO];

    float sE = 0.f, sO = 0.f, qE = 0.f, qO = 0.f;   // groups 2*oq, 2*oq+1

#pragma unroll
    for (int it = 0; it < 4; it++) {
        const int c = it * 16 + vz;
        const int v = v0 + c;
        float4 a = make_float4(0.f, 0.f, 0.f, 0.f);
        if (v < NV) {
            a = bo4;
            if (v < NVP) {
                uint2 r0 = *(const uint2*)&zb[(size_t)v * MO + o4];
                float2 z0 = h2f(r0.x), z1 = h2f(r0.y);
                a.x += z0.x; a.y += z0.y; a.z += z1.x; a.w += z1.y;
            }
            const int cnt = s_cnt[c];
            const float4* pk = &s_pack[c * KN];
            for (int j = 0; j < cnt; j++) {
                float4 e = pk[j];
                const __half* zp = zb + __float_as_int(e.x) + o4;
                uint2 r1 = *(const uint2*)(zp + 64);
                uint2 r2 = *(const uint2*)(zp + 128);
                uint2 r3 = *(const uint2*)(zp + 192);
                float2 a1 = h2f(r1.x), b1 = h2f(r1.y);
                float2 a2 = h2f(r2.x), b2 = h2f(r2.y);
                float2 a3 = h2f(r3.x), b3 = h2f(r3.y);
                a.x += e.y * a1.x + e.z * a2.x + e.w * a3.x;
                a.y += e.y * a1.y + e.z * a2.y + e.w * a3.y;
                a.z += e.y * b1.x + e.z * b2.x + e.w * b3.x;
                a.w += e.y * b1.y + e.z * b2.y + e.w * b3.y;
            }
            sE += a.x + a.y; qE += a.x * a.x + a.y * a.y;
            sO += a.z + a.w; qO += a.z * a.z + a.w * a.w;
        }
        smt[o4 + 0][c] = a.x;
        smt[o4 + 1][c] = a.y;
        smt[o4 + 2][c] = a.z;
        smt[o4 + 3][c] = a.w;
    }

    // lanes l and l+16 share oq -> fold, then one atomic set per oq
    sE += __shfl_down_sync(0xffffffffu, sE, 16);
    sO += __shfl_down_sync(0xffffffffu, sO, 16);
    qE += __shfl_down_sync(0xffffffffu, qE, 16);
    qO += __shfl_down_sync(0xffffffffu, qO, 16);
    if ((t & 31) < 16) {
        atomicAdd(&s_s[2 * oq],     sE);
        atomicAdd(&s_s[2 * oq + 1], sO);
        atomicAdd(&s_q[2 * oq],     qE);
        atomicAdd(&s_q[2 * oq + 1], qO);
    }
    __syncthreads();
    if (t < NGROUPS) {
        atomicAdd(&g_sum[b * NGROUPS + t],   s_s[t]);
        atomicAdd(&g_sumsq[b * NGROUPS + t], s_q[t]);
    }

    // coalesced float2 store of the (b, o, v0..v0+63) tile
#pragma unroll
    for (int k = 0; k < 8; k++) {
        int idx = t + k * 256;
        int oo = idx >> 5;          // 64 rows
        int c2 = idx & 31;          // 32 float2 per row
        int v  = v0 + c2 * 2;
        if (v < NV) {               // NV even: pairs never split
            float2 val = make_float2(smt[oo][c2 * 2], smt[oo][c2 * 2 + 1]);
            *(float2*)&out[((size_t)b * COUT + oo) * NV + v] = val;
        }
    }
}

// ---------------- K3: GroupNorm affine + ReLU (a,c computed per block) -------
// grid: (chunks, BB*COUT rows). Each block = one row chunk; thread 0 derives
// the row's affine from g_sum/g_sumsq, loop is a pure float2 stream (ILP 10).
__global__ __launch_bounds__(256) void k_norm(float* __restrict__ out,
                                              const float* __restrict__ gamma,
                                              const float* __restrict__ beta)
{
    __shared__ float sa, sc;
    const int row = blockIdx.y;                 // b*64 + o
    if (threadIdx.x == 0) {
        int o = row & 63;
        int g = (row >> 6) * NGROUPS + (o >> 1);
        const float invN = 1.f / (2.f * (float)NV);
        float mean = g_sum[g] * invN;
        float var  = g_sumsq[g] * invN - mean * mean;
        float inv  = rsqrtf(var + EPS);
        float a = inv * gamma[o];
        sa = a;
        sc = beta[o] - mean * a;
    }
    __syncthreads();
    const float a = sa, c = sc;

    float2* rp = (float2*)(out + (size_t)row * NV);
    const int base = blockIdx.x * 2560 + threadIdx.x;
#pragma unroll
    for (int j = 0; j < 10; j++) {
        int p = base + j * 256;
        if (p < HALFNV) {
            float2 v = rp[p];
            v.x = fmaxf(v.x * a + c, 0.f);
            v.y = fmaxf(v.y * a + c, 0.f);
            rp[p] = v;
        }
    }
}

// ---------------- launch ----------------
extern "C" void kernel_launch(void* const* d_in, const int* in_sizes, int n_in,
                              void* d_out, int out_size) {
    const float* x      = (const float*)d_in[0];
    const float* Lv     = (const float*)d_in[1];
    const float* EWv    = (const float*)d_in[2];
    const float* NSv    = (const float*)d_in[3];
    const float* coeffs = (const float*)d_in[4];
    const float* bias   = (const float*)d_in[5];
    const float* gamma  = (const float*)d_in[6];
    const float* beta   = (const float*)d_in[7];
    const int*   nbr    = (const int*)d_in[8];
    float* out = (float*)d_out;

    k_prep<<<(NV + 255) / 256, 256>>>(coeffs, nbr, Lv, EWv, NSv);

    dim3 g1((NVP + 63) / 64, BB);
    k_gemm<<<g1, 256>>>(x);

    dim3 g2((NV + 63) / 64, BB);
    k_gather<<<g2, 256>>>(bias, out);

    dim3 g3((HALFNV + 2559) / 2560, BB * COUT);   // (9, 512)
    k_norm<<<g3, 256>>>(out, gamma, beta);
}